// round 14
// baseline (speedup 1.0000x reference)
#include <cuda_runtime.h>
#include <cuda_fp16.h>
#include <math.h>

#define TT   2048
#define HD   1024
#define ID   2816
#define NE   8
#define ISD  1408

// ---- routing scratch ----
__device__ int   g_count[NE];
__device__ int   g_tok[NE][TT];
__device__ int   g_slot[NE][TT];
__device__ int   g_top0[TT];
__device__ int   g_top1[TT];
__device__ float g_p[TT][2];
__device__ float g_dp0[(size_t)TT * 2 * HD];
__device__ float g_dp1[(size_t)TT * 2 * HD];

// ---- fp16 operands ----
__device__ __half g_Wg16[(size_t)NE * HD * ID];
__device__ __half g_Wu16[(size_t)NE * HD * ID];
__device__ __half g_Wd16[(size_t)NE * ID * HD];
__device__ __half g_Sg16[(size_t)HD * ISD];
__device__ __half g_Su16[(size_t)HD * ISD];
__device__ __half g_Sd16[(size_t)ISD * HD];
__device__ __half g_x16[(size_t)TT * HD];
__device__ __half g_act[(size_t)TT * 2 * ID];
__device__ __half g_shact[(size_t)TT * ISD];

// ---- global barrier state ----
__device__ unsigned g_arrive = 0;
__device__ unsigned g_gen = 0;

// =================== helpers ===================
__device__ __forceinline__ unsigned s2u(const void* p) {
    return (unsigned)__cvta_generic_to_shared(p);
}
__device__ __forceinline__ unsigned swz(unsigned o) { return o ^ ((o >> 3) & 0x70); }

__device__ __forceinline__ unsigned pack2h(float f0, float f1) {
    __half2 h = __floats2half2_rn(f0, f1);
    return *(unsigned*)&h;
}
__device__ __forceinline__ void cpasync16(unsigned s, const void* g) {
    asm volatile("cp.async.cg.shared.global [%0], [%1], 16;" :: "r"(s), "l"(g));
}
#define CP_COMMIT() asm volatile("cp.async.commit_group;" ::: "memory")
#define CP_WAIT1()  asm volatile("cp.async.wait_group 1;"  ::: "memory")
#define CP_WAIT0()  asm volatile("cp.async.wait_group 0;"  ::: "memory")

__device__ __forceinline__ void ldsm4(unsigned a, unsigned* r) {
    asm volatile("ldmatrix.sync.aligned.m8n8.x4.shared.b16 {%0,%1,%2,%3}, [%4];"
                 : "=r"(r[0]), "=r"(r[1]), "=r"(r[2]), "=r"(r[3]) : "r"(a));
}
__device__ __forceinline__ void ldsm4t(unsigned a, unsigned* r) {
    asm volatile("ldmatrix.sync.aligned.m8n8.x4.trans.shared.b16 {%0,%1,%2,%3}, [%4];"
                 : "=r"(r[0]), "=r"(r[1]), "=r"(r[2]), "=r"(r[3]) : "r"(a));
}
__device__ __forceinline__ void mma16816(float* c, const unsigned* a, const unsigned* b) {
    asm volatile("mma.sync.aligned.m16n8k16.row.col.f32.f16.f16.f32 "
                 "{%0,%1,%2,%3}, {%4,%5,%6,%7}, {%8,%9}, {%0,%1,%2,%3};"
                 : "+f"(c[0]), "+f"(c[1]), "+f"(c[2]), "+f"(c[3])
                 : "r"(a[0]), "r"(a[1]), "r"(a[2]), "r"(a[3]), "r"(b[0]), "r"(b[1]));
}
__device__ __forceinline__ float silu_mul(float g, float u) {
    return u * g / (1.f + __expf(-g));
}

// device-wide barrier (all gridDim.x CTAs co-resident by construction)
__device__ __forceinline__ void gbar() {
    __syncthreads();
    if (threadIdx.x == 0) {
        __threadfence();
        unsigned gen = atomicAdd(&g_gen, 0u);
        if (atomicAdd(&g_arrive, 1u) == (unsigned)gridDim.x - 1u) {
            g_arrive = 0;
            __threadfence();
            atomicAdd(&g_gen, 1u);
        } else {
            while (atomicAdd(&g_gen, 0u) == gen) __nanosleep(64);
        }
    }
    __syncthreads();
}

// =================== P0: conversions + router logits ===================
#define NXC (TT * HD / 8)
#define NWC (NE * HD * ID / 8)
#define NSC (HD * ISD / 8)
#define CONV_TOTAL (NXC + 3L * NWC + 3L * NSC)

__device__ void p0_conv_router(const float* xf, const float* gw,
                               const float4* x4, const float4* wg, const float4* wu,
                               const float4* wd, const float4* sg, const float4* su,
                               const float4* sd) {
    long gtid = (long)blockIdx.x * blockDim.x + threadIdx.x;
    long stride = (long)gridDim.x * blockDim.x;

    if (gtid < TT) {
        int t = (int)gtid;
        float lg[NE];
#pragma unroll
        for (int e = 0; e < NE; e++) lg[e] = 0.f;
        const float* xr = xf + (size_t)t * HD;
        for (int h = 0; h < HD; h++) {
            float xv = xr[h];
#pragma unroll
            for (int e = 0; e < NE; e++) lg[e] = fmaf(xv, gw[h * NE + e], lg[e]);
        }
        int i0 = 0; float v0 = lg[0];
#pragma unroll
        for (int e = 1; e < NE; e++) if (lg[e] > v0) { v0 = lg[e]; i0 = e; }
        int i1 = -1; float v1 = -INFINITY;
#pragma unroll
        for (int e = 0; e < NE; e++) if (e != i0 && lg[e] > v1) { v1 = lg[e]; i1 = e; }
        float e1 = expf(v1 - v0);
        float inv = 1.f / (1.f + e1);
        g_p[t][0] = inv;
        g_p[t][1] = e1 * inv;
        g_top0[t] = i0;
        g_top1[t] = i1;
    }

    for (long i0 = gtid; i0 < CONV_TOTAL; i0 += stride) {
        long i = i0;
        const float4* src; __half* dst;
        if (i < NXC)               { src = x4; dst = g_x16; }
        else if ((i -= NXC) < NWC) { src = wg; dst = g_Wg16; }
        else if ((i -= NWC) < NWC) { src = wu; dst = g_Wu16; }
        else if ((i -= NWC) < NWC) { src = wd; dst = g_Wd16; }
        else if ((i -= NWC) < NSC) { src = sg; dst = g_Sg16; }
        else if ((i -= NSC) < NSC) { src = su; dst = g_Su16; }
        else                       { i -= NSC; src = sd; dst = g_Sd16; }
        float4 a = src[2 * i], b = src[2 * i + 1];
        uint4 o;
        o.x = pack2h(a.x, a.y);
        o.y = pack2h(a.z, a.w);
        o.z = pack2h(b.x, b.y);
        o.w = pack2h(b.z, b.w);
        ((uint4*)dst)[i] = o;
    }
}

// =================== P0b: deterministic list build (CTA 0, warp e = expert e) ===================
__device__ void p0b_build_lists() {
    int lane = threadIdx.x & 31;
    int e = threadIdx.x >> 5;           // 8 warps = 8 experts
    int base = 0;
    for (int c = 0; c < TT / 32; c++) {
        int t = c * 32 + lane;
        bool f0 = (g_top0[t] == e);
        bool f1 = (g_top1[t] == e);
        unsigned m0 = __ballot_sync(0xFFFFFFFFu, f0);
        unsigned m1 = __ballot_sync(0xFFFFFFFFu, f1);
        unsigned lt = (1u << lane) - 1u;
        if (f0) { int p = base + __popc(m0 & lt); g_tok[e][p] = t; g_slot[e][p] = 0; }
        int b0 = base + __popc(m0);
        if (f1) { int p = b0 + __popc(m1 & lt); g_tok[e][p] = t; g_slot[e][p] = 1; }
        base = b0 + __popc(m1);
    }
    if (lane == 0) g_count[e] = base;
}

// =================== P1 tile: gate+up (BM=128, BN=64) ===================
#define GU_A  0u
#define GU_BG 16384u
#define GU_BU 24576u
#define GU_STG 32768u

__device__ void gu_tile(int bx, int by, int bz, unsigned sb) {
    constexpr int NK = HD / 64;
    const int tid = threadIdx.x, l = tid & 31, wid = tid >> 5;
    const int m0 = bx * 128, n0 = by * 64;
    const int e = bz;
    const bool SH = (e == NE);
    const int N_TOT = SH ? ISD : ID;
    int cnt = TT;
    if (SH) { if (n0 >= ISD) return; }
    else    { cnt = g_count[e]; if (m0 >= cnt) return; }

    const __half* Bg = (SH ? g_Sg16 : g_Wg16 + (size_t)e * HD * ID) + n0;
    const __half* Bu = (SH ? g_Su16 : g_Wu16 + (size_t)e * HD * ID) + n0;

    size_t aoff[4];
#pragma unroll
    for (int p = 0; p < 4; p++) {
        int idx = m0 + p * 32 + (tid >> 3);
        if (!SH) {
            int ci = idx < cnt ? idx : cnt - 1;
            aoff[p] = (size_t)g_tok[e][ci] * HD;
        } else {
            aoff[p] = (size_t)idx * HD;
        }
    }

    const int kseg = tid & 7;
    auto LOAD = [&](int kt) {
        unsigned bb = sb + (unsigned)(kt % 3) * GU_STG;
        int k0 = kt * 64;
#pragma unroll
        for (int i = 0; i < 4; i++) {
            unsigned d = swz((unsigned)(i * 32 + (tid >> 3)) * 128 + kseg * 16);
            cpasync16(bb + GU_A + d, g_x16 + aoff[i] + k0 + kseg * 8);
        }
#pragma unroll
        for (int i = 0; i < 2; i++) {
            int s = i * 256 + tid;
            int kk = s >> 3, c8 = s & 7;
            unsigned d = swz((unsigned)kk * 128 + c8 * 16);
            size_t o = (size_t)(k0 + kk) * N_TOT + c8 * 8;
            cpasync16(bb + GU_BG + d, Bg + o);
            cpasync16(bb + GU_BU + d, Bu + o);
        }
        CP_COMMIT();
    };

    float cg[2][4][4] = {}, cu[2][4][4] = {};
    const int wm = (wid & 3) * 32, wn = (wid >> 2) * 32;
    const unsigned aRowB = (unsigned)(wm + (l & 15)) * 128;
    const unsigned sx = l & 7;
    const unsigned aCx = (l >> 4) & 1;
    const unsigned bKr = (l & 7) + ((l >> 3) & 1) * 8;
    const unsigned bG2 = (l >> 4) & 1;
    const unsigned nq = (unsigned)wn >> 3;
    const unsigned ck0 = ((nq + 0 + bG2) ^ sx) << 4;
    const unsigned ck1 = ((nq + 2 + bG2) ^ sx) << 4;

    auto COMPUTE = [&](int st) {
        unsigned bb = sb + (unsigned)st * GU_STG;
#pragma unroll
        for (int ks = 0; ks < 4; ks++) {
            unsigned cka = (((unsigned)(ks * 2) + aCx) ^ sx) << 4;
            unsigned ah[2][4];
#pragma unroll
            for (int mf = 0; mf < 2; mf++)
                ldsm4(bb + GU_A + aRowB + mf * 2048 + cka, ah[mf]);
            unsigned brow = (unsigned)(ks * 16 + bKr) * 128;
            unsigned bg[8], bu[8];
            ldsm4t(bb + GU_BG + brow + ck0, bg);
            ldsm4t(bb + GU_BG + brow + ck1, bg + 4);
            ldsm4t(bb + GU_BU + brow + ck0, bu);
            ldsm4t(bb + GU_BU + brow + ck1, bu + 4);
#pragma unroll
            for (int mf = 0; mf < 2; mf++)
#pragma unroll
                for (int nf = 0; nf < 4; nf++) {
                    mma16816(cg[mf][nf], ah[mf], bg + nf * 2);
                    mma16816(cu[mf][nf], ah[mf], bu + nf * 2);
                }
        }
    };

    LOAD(0);
    LOAD(1);
#pragma unroll 1
    for (int kt = 0; kt < NK; kt++) {
        if (kt + 1 < NK) CP_WAIT1(); else CP_WAIT0();
        __syncthreads();
        if (kt + 2 < NK) LOAD(kt + 2);
        COMPUTE(kt % 3);
    }

    const int rr = m0 + wm + (l >> 2);
    const int cc0 = n0 + wn + (l & 3) * 2;
    __half* O = SH ? g_shact : g_act;
#pragma unroll
    for (int mf = 0; mf < 2; mf++) {
#pragma unroll
        for (int h = 0; h < 2; h++) {
            int r = rr + mf * 16 + h * 8;
            size_t obase;
            if (!SH) {
                if (r >= cnt) continue;
                int flat = g_tok[e][r] * 2 + g_slot[e][r];
                obase = (size_t)flat * ID;
            } else {
                obase = (size_t)r * ISD;
            }
#pragma unroll
            for (int nf = 0; nf < 4; nf++) {
                float a0 = silu_mul(cg[mf][nf][h * 2 + 0], cu[mf][nf][h * 2 + 0]);
                float a1 = silu_mul(cg[mf][nf][h * 2 + 1], cu[mf][nf][h * 2 + 1]);
                *(unsigned*)(O + obase + cc0 + nf * 8) = pack2h(a0, a1);
            }
        }
    }
    __syncthreads();   // protect smem ring before next tile
}

// =================== P2 tile: expert down, split-K x2 (BM=128, BN=128) ===================
#define DN_A 0u
#define DN_B 16384u
#define DN_STG 32768u

__device__ void ed_tile(int bx, int by, int bz, unsigned sb) {
    const int tid = threadIdx.x, l = tid & 31, wid = tid >> 5;
    const int m0 = bx * 128, n0 = by * 128;
    const int e = bz >> 1, s = bz & 1;
    const int nkt = ID / 128;          // 22 k-tiles of 64 per split
    const int kb  = s * (ID / 2);
    int cnt = g_count[e];
    if (m0 >= cnt) return;

    const __half* B = g_Wd16 + (size_t)e * ID * HD + (size_t)kb * HD + n0;

    size_t aoff[4];
#pragma unroll
    for (int p = 0; p < 4; p++) {
        int idx = m0 + p * 32 + (tid >> 3);
        int ci = idx < cnt ? idx : cnt - 1;
        aoff[p] = (size_t)(g_tok[e][ci] * 2 + g_slot[e][ci]) * ID + kb;
    }

    const int kseg = tid & 7;
    auto LOAD = [&](int kt) {
        unsigned bb = sb + (unsigned)(kt % 3) * DN_STG;
        int k0 = kt * 64;
#pragma unroll
        for (int i = 0; i < 4; i++) {
            unsigned d = swz((unsigned)(i * 32 + (tid >> 3)) * 128 + kseg * 16);
            cpasync16(bb + DN_A + d, g_act + aoff[i] + k0 + kseg * 8);
        }
#pragma unroll
        for (int i = 0; i < 4; i++) {
            int sidx = i * 256 + tid;
            int kk = sidx >> 4, c16 = sidx & 15;
            unsigned d = (unsigned)(c16 >> 3) * 8192 + swz((unsigned)kk * 128 + (c16 & 7) * 16);
            cpasync16(bb + DN_B + d, B + (size_t)(k0 + kk) * HD + c16 * 8);
        }
        CP_COMMIT();
    };

    float cc[2][8][4] = {};
    const int wm = (wid & 3) * 32, wn = (wid >> 2) * 64;
    const unsigned aRowB = (unsigned)(wm + (l & 15)) * 128;
    const unsigned sx = l & 7;
    const unsigned aCx = (l >> 4) & 1;
    const unsigned bKr = (l & 7) + ((l >> 3) & 1) * 8;
    const unsigned bG2 = (l >> 4) & 1;
    const unsigned hoff = (unsigned)(wn >> 6) * 8192;
    unsigned ck[4];
#pragma unroll
    for (int j = 0; j < 4; j++) ck[j] = (((unsigned)(2 * j) + bG2) ^ sx) << 4;

    auto COMPUTE = [&](int st) {
        unsigned bb = sb + (unsigned)st * DN_STG;
#pragma unroll
        for (int ks = 0; ks < 4; ks++) {
            unsigned cka = (((unsigned)(ks * 2) + aCx) ^ sx) << 4;
            unsigned ah[2][4];
#pragma unroll
            for (int mf = 0; mf < 2; mf++)
                ldsm4(bb + DN_A + aRowB + mf * 2048 + cka, ah[mf]);
            unsigned brow = (unsigned)(ks * 16 + bKr) * 128;
            unsigned bh[16];
#pragma unroll
            for (int j = 0; j < 4; j++)
                ldsm4t(bb + DN_B + hoff + brow + ck[j], bh + 4 * j);
#pragma unroll
            for (int mf = 0; mf < 2; mf++)
#pragma unroll
                for (int nf = 0; nf < 8; nf++)
                    mma16816(cc[mf][nf], ah[mf], bh + nf * 2);
        }
    };

    LOAD(0);
    LOAD(1);
#pragma unroll 1
    for (int kt = 0; kt < nkt; kt++) {
        if (kt + 1 < nkt) CP_WAIT1(); else CP_WAIT0();
        __syncthreads();
        if (kt + 2 < nkt) LOAD(kt + 2);
        COMPUTE(kt % 3);
    }

    const int rr = m0 + wm + (l >> 2);
    const int cc0 = n0 + wn + (l & 3) * 2;
    float* OutP = s ? g_dp1 : g_dp0;
#pragma unroll
    for (int mf = 0; mf < 2; mf++) {
#pragma unroll
        for (int h = 0; h < 2; h++) {
            int r = rr + mf * 16 + h * 8;
            if (r >= cnt) continue;
            int tok = g_tok[e][r], slot = g_slot[e][r];
            float pw = g_p[tok][slot];
            size_t base = (size_t)(tok * 2 + slot) * HD;
#pragma unroll
            for (int nf = 0; nf < 8; nf++) {
                size_t off = base + cc0 + nf * 8;
                *(float2*)(OutP + off) =
                    make_float2(pw * cc[mf][nf][h * 2 + 0], pw * cc[mf][nf][h * 2 + 1]);
            }
        }
    }
    __syncthreads();
}

// =================== P3 tile: shared down + fused combine (BM=64, BN=128) ===================
#define SD_A 0u
#define SD_B 8192u
#define SD_STG 24576u

__device__ void sd_tile(int bx, int by, unsigned sb, float* __restrict__ Out) {
    constexpr int NK = ISD / 64;       // 22
    const int tid = threadIdx.x, l = tid & 31, wid = tid >> 5;
    const int m0 = bx * 64, n0 = by * 128;

    const __half* B = g_Sd16 + n0;

    size_t aoff[2];
#pragma unroll
    for (int p = 0; p < 2; p++) {
        int idx = m0 + p * 32 + (tid >> 3);
        aoff[p] = (size_t)idx * ISD;
    }

    const int kseg = tid & 7;
    auto LOAD = [&](int kt) {
        unsigned bb = sb + (unsigned)(kt % 3) * SD_STG;
        int k0 = kt * 64;
#pragma unroll
        for (int i = 0; i < 2; i++) {
            unsigned d = swz((unsigned)(i * 32 + (tid >> 3)) * 128 + kseg * 16);
            cpasync16(bb + SD_A + d, g_shact + aoff[i] + k0 + kseg * 8);
        }
#pragma unroll
        for (int i = 0; i < 4; i++) {
            int sidx = i * 256 + tid;
            int kk = sidx >> 4, c16 = sidx & 15;
            unsigned d = (unsigned)(c16 >> 3) * 8192 + swz((unsigned)kk * 128 + (c16 & 7) * 16);
            cpasync16(bb + SD_B + d, B + (size_t)(k0 + kk) * HD + c16 * 8);
        }
        CP_COMMIT();
    };

    float cc[2][4][4] = {};
    const int wm = (wid & 1) * 32, wn = (wid >> 1) * 32;
    const unsigned aRowB = (unsigned)(wm + (l & 15)) * 128;
    const unsigned sx = l & 7;
    const unsigned aCx = (l >> 4) & 1;
    const unsigned bKr = (l & 7) + ((l >> 3) & 1) * 8;
    const unsigned bG2 = (l >> 4) & 1;
    const unsigned hoff = (unsigned)(wn >> 6) * 8192;
    const unsigned nq = ((unsigned)wn & 63) >> 3;
    const unsigned ck0 = ((nq + 0 + bG2) ^ sx) << 4;
    const unsigned ck1 = ((nq + 2 + bG2) ^ sx) << 4;

    auto COMPUTE = [&](int st) {
        unsigned bb = sb + (unsigned)st * SD_STG;
#pragma unroll
        for (int ks = 0; ks < 4; ks++) {
            unsigned cka = (((unsigned)(ks * 2) + aCx) ^ sx) << 4;
            unsigned ah[2][4];
#pragma unroll
            for (int mf = 0; mf < 2; mf++)
                ldsm4(bb + SD_A + aRowB + mf * 2048 + cka, ah[mf]);
            unsigned brow = (unsigned)(ks * 16 + bKr) * 128;
            unsigned bh[8];
            ldsm4t(bb + SD_B + hoff + brow + ck0, bh);
            ldsm4t(bb + SD_B + hoff + brow + ck1, bh + 4);
#pragma unroll
            for (int mf = 0; mf < 2; mf++)
#pragma unroll
                for (int nf = 0; nf < 4; nf++)
                    mma16816(cc[mf][nf], ah[mf], bh + nf * 2);
        }
    };

    LOAD(0);
    LOAD(1);
#pragma unroll 1
    for (int kt = 0; kt < NK; kt++) {
        if (kt + 1 < NK) CP_WAIT1(); else CP_WAIT0();
        __syncthreads();
        if (kt + 2 < NK) LOAD(kt + 2);
        COMPUTE(kt % 3);
    }

    const int rr = m0 + wm + (l >> 2);
    const int cc0 = n0 + wn + (l & 3) * 2;
#pragma unroll
    for (int mf = 0; mf < 2; mf++) {
#pragma unroll
        for (int h = 0; h < 2; h++) {
            int r = rr + mf * 16 + h * 8;
            const float* a0 = g_dp0 + (size_t)(2 * r) * HD;
            const float* a1 = a0 + HD;
            const float* b0 = g_dp1 + (size_t)(2 * r) * HD;
            const float* b1 = b0 + HD;
#pragma unroll
            for (int nf = 0; nf < 4; nf++) {
                int col = cc0 + nf * 8;
                float2 v0 = *(const float2*)(a0 + col);
                float2 v1 = *(const float2*)(a1 + col);
                float2 v2 = *(const float2*)(b0 + col);
                float2 v3 = *(const float2*)(b1 + col);
                float2 o;
                o.x = cc[mf][nf][h * 2 + 0] + v0.x + v1.x + v2.x + v3.x;
                o.y = cc[mf][nf][h * 2 + 1] + v0.y + v1.y + v2.y + v3.y;
                *(float2*)(Out + (size_t)r * HD + col) = o;
            }
        }
    }
    __syncthreads();
}

// =================== megakernel ===================
#define GU_TILES (16 * 44 * 9)
#define ED_TILES (16 * 8 * 16)
#define SD_TILES (32 * 8)

__global__ void __launch_bounds__(256, 2) mega(
    const float* __restrict__ x, const float* __restrict__ gw,
    const float* __restrict__ Wg, const float* __restrict__ Wu,
    const float* __restrict__ Wd, const float* __restrict__ Sg,
    const float* __restrict__ Su, const float* __restrict__ Sd,
    float* __restrict__ out) {
    extern __shared__ char dyn[];
    unsigned sb = (s2u(dyn) + 127) & ~127u;

    // P0: conversions + router logits
    p0_conv_router(x, gw,
                   (const float4*)x,  (const float4*)Wg, (const float4*)Wu,
                   (const float4*)Wd, (const float4*)Sg, (const float4*)Su,
                   (const float4*)Sd);
    gbar();

    // P0b: deterministic per-expert list build
    if (blockIdx.x == 0) p0b_build_lists();
    gbar();

    // P1: gate+up (expert z=0..7, shared z=8)
    for (int t = blockIdx.x; t < GU_TILES; t += gridDim.x) {
        int bx = t & 15, r = t >> 4;
        gu_tile(bx, r % 44, r / 44, sb);
    }
    gbar();

    // P2: expert down, split-K x2
    for (int t = blockIdx.x; t < ED_TILES; t += gridDim.x) {
        int bx = t & 15, r = t >> 4;
        ed_tile(bx, r & 7, r >> 3, sb);
    }
    gbar();

    // P3: shared down + fused final combine
    for (int t = blockIdx.x; t < SD_TILES; t += gridDim.x) {
        sd_tile(t & 31, t >> 5, sb, out);
    }
}

// =================== launch ===================
extern "C" void kernel_launch(void* const* d_in, const int* in_sizes, int n_in,
                              void* d_out, int out_size) {
    const float* x      = (const float*)d_in[0];
    const float* gate_w = (const float*)d_in[1];
    const float* Wg     = (const float*)d_in[2];
    const float* Wu     = (const float*)d_in[3];
    const float* Wd     = (const float*)d_in[4];
    const float* Sg     = (const float*)d_in[5];
    const float* Su     = (const float*)d_in[6];
    const float* Sd     = (const float*)d_in[7];
    float* out = (float*)d_out;

    const int SMEM = 3 * 32768 + 128;   // 98432
    cudaFuncSetAttribute(mega, cudaFuncAttributeMaxDynamicSharedMemorySize, SMEM);

    int sms = 0;
    cudaDeviceGetAttribute(&sms, cudaDevAttrMultiProcessorCount, 0);
    int maxb = 0;
    cudaOccupancyMaxActiveBlocksPerMultiprocessor(&maxb, mega, 256, SMEM);
    if (maxb < 1) maxb = 1;
    if (maxb > 2) maxb = 2;
    int ncta = sms * maxb;

    mega<<<ncta, 256, SMEM>>>(x, gate_w, Wg, Wu, Wd, Sg, Su, Sd, out);
}

// round 15
// speedup vs baseline: 2.1491x; 2.1491x over previous
#include <cuda_runtime.h>
#include <cuda_fp16.h>
#include <math.h>

#define TT   2048
#define HD   1024
#define ID   2816
#define NE   8
#define ISD  1408

// ---- routing scratch ----
__device__ int   g_count[NE];
__device__ int   g_tok[NE][TT];
__device__ int   g_slot[NE][TT];
__device__ float g_p[TT][2];
__device__ float g_dp0[(size_t)TT * 2 * HD];   // split-K partial 0 (p-weighted)
__device__ float g_dp1[(size_t)TT * 2 * HD];   // split-K partial 1 (p-weighted)

// ---- fp16 operands ----
__device__ __half g_Wg16[(size_t)NE * HD * ID];
__device__ __half g_Wu16[(size_t)NE * HD * ID];
__device__ __half g_Wd16[(size_t)NE * ID * HD];
__device__ __half g_Sg16[(size_t)HD * ISD];
__device__ __half g_Su16[(size_t)HD * ISD];
__device__ __half g_Sd16[(size_t)ISD * HD];
__device__ __half g_x16[(size_t)TT * HD];
__device__ __half g_act[(size_t)TT * 2 * ID];
__device__ __half g_shact[(size_t)TT * ISD];

// =================== helpers ===================
__device__ __forceinline__ unsigned s2u(const void* p) {
    return (unsigned)__cvta_generic_to_shared(p);
}
__device__ __forceinline__ unsigned swz(unsigned o) { return o ^ ((o >> 3) & 0x70); }

__device__ __forceinline__ unsigned pack2h(float f0, float f1) {
    __half2 h = __floats2half2_rn(f0, f1);
    return *(unsigned*)&h;
}
__device__ __forceinline__ void cpasync16(unsigned s, const void* g) {
    asm volatile("cp.async.cg.shared.global [%0], [%1], 16;" :: "r"(s), "l"(g));
}
#define CP_COMMIT() asm volatile("cp.async.commit_group;" ::: "memory")
#define CP_WAIT1()  asm volatile("cp.async.wait_group 1;"  ::: "memory")
#define CP_WAIT0()  asm volatile("cp.async.wait_group 0;"  ::: "memory")

__device__ __forceinline__ void ldsm4(unsigned a, unsigned* r) {
    asm volatile("ldmatrix.sync.aligned.m8n8.x4.shared.b16 {%0,%1,%2,%3}, [%4];"
                 : "=r"(r[0]), "=r"(r[1]), "=r"(r[2]), "=r"(r[3]) : "r"(a));
}
__device__ __forceinline__ void ldsm4t(unsigned a, unsigned* r) {
    asm volatile("ldmatrix.sync.aligned.m8n8.x4.trans.shared.b16 {%0,%1,%2,%3}, [%4];"
                 : "=r"(r[0]), "=r"(r[1]), "=r"(r[2]), "=r"(r[3]) : "r"(a));
}
__device__ __forceinline__ void mma16816(float* c, const unsigned* a, const unsigned* b) {
    asm volatile("mma.sync.aligned.m16n8k16.row.col.f32.f16.f16.f32 "
                 "{%0,%1,%2,%3}, {%4,%5,%6,%7}, {%8,%9}, {%0,%1,%2,%3};"
                 : "+f"(c[0]), "+f"(c[1]), "+f"(c[2]), "+f"(c[3])
                 : "r"(a[0]), "r"(a[1]), "r"(a[2]), "r"(a[3]), "r"(b[0]), "r"(b[1]));
}
__device__ __forceinline__ float silu_mul(float g, float u) {
    return u * g / (1.f + __expf(-g));
}

// =================== conversion kernels ===================
#define NXC (TT * HD / 8)
#define NWC (NE * HD * ID / 8)
#define NSC (HD * ISD / 8)

// main-stream: x, Wg, Wu
__global__ void conv_a(const float4* __restrict__ x, const float4* __restrict__ wg,
                       const float4* __restrict__ wu) {
    long i = (long)blockIdx.x * blockDim.x + threadIdx.x;
    const float4* src; __half* dst;
    if (i < NXC)               { src = x;  dst = g_x16; }
    else if ((i -= NXC) < NWC) { src = wg; dst = g_Wg16; }
    else if ((i -= NWC) < NWC) { src = wu; dst = g_Wu16; }
    else return;
    float4 a = src[2 * i], b = src[2 * i + 1];
    uint4 o;
    o.x = pack2h(a.x, a.y);
    o.y = pack2h(a.z, a.w);
    o.z = pack2h(b.x, b.y);
    o.w = pack2h(b.z, b.w);
    ((uint4*)dst)[i] = o;
}
#define CONVA_TOTAL (NXC + 2 * NWC)

// side-stream: Wd, Sg, Su, Sd
__global__ void conv_b(const float4* __restrict__ wd, const float4* __restrict__ sg,
                       const float4* __restrict__ su, const float4* __restrict__ sd) {
    long i = (long)blockIdx.x * blockDim.x + threadIdx.x;
    const float4* src; __half* dst;
    if (i < NWC)               { src = wd; dst = g_Wd16; }
    else if ((i -= NWC) < NSC) { src = sg; dst = g_Sg16; }
    else if ((i -= NSC) < NSC) { src = su; dst = g_Su16; }
    else if ((i -= NSC) < NSC) { src = sd; dst = g_Sd16; }
    else return;
    float4 a = src[2 * i], b = src[2 * i + 1];
    uint4 o;
    o.x = pack2h(a.x, a.y);
    o.y = pack2h(a.z, a.w);
    o.z = pack2h(b.x, b.y);
    o.w = pack2h(b.z, b.w);
    ((uint4*)dst)[i] = o;
}
#define CONVB_TOTAL (NWC + 3 * NSC)

// =================== router ===================
__global__ void zero_counts_kernel() { if (threadIdx.x < NE) g_count[threadIdx.x] = 0; }

__global__ void router_kernel(const float* __restrict__ x, const float* __restrict__ gw) {
    int t = blockIdx.x * blockDim.x + threadIdx.x;
    if (t >= TT) return;
    float lg[NE];
#pragma unroll
    for (int e = 0; e < NE; e++) lg[e] = 0.f;
    const float* xr = x + (size_t)t * HD;
    for (int h = 0; h < HD; h++) {
        float xv = xr[h];
#pragma unroll
        for (int e = 0; e < NE; e++) lg[e] = fmaf(xv, gw[h * NE + e], lg[e]);
    }
    int i0 = 0; float v0 = lg[0];
#pragma unroll
    for (int e = 1; e < NE; e++) if (lg[e] > v0) { v0 = lg[e]; i0 = e; }
    int i1 = -1; float v1 = -INFINITY;
#pragma unroll
    for (int e = 0; e < NE; e++) if (e != i0 && lg[e] > v1) { v1 = lg[e]; i1 = e; }
    float e1 = expf(v1 - v0);
    float inv = 1.f / (1.f + e1);
    g_p[t][0] = inv;
    g_p[t][1] = e1 * inv;
    int p0 = atomicAdd(&g_count[i0], 1);
    g_tok[i0][p0] = t; g_slot[i0][p0] = 0;
    int p1 = atomicAdd(&g_count[i1], 1);
    g_tok[i1][p1] = t; g_slot[i1][p1] = 1;
}

// =================== gate+up HMMA (256 thr, BM=128, BN=64, 2 CTAs/SM) ===================
// SH=false: expert (z = expert id, gathered rows, out -> g_act fp16)
// SH=true : shared (2D grid, out -> g_shact fp16)
#define GU_A  0u
#define GU_BG 16384u
#define GU_BU 24576u
#define GU_STG 32768u

template<bool SH>
__global__ void __launch_bounds__(256, 2) gateup_hmma() {
    constexpr int NK = HD / 64;
    constexpr int N_TOT = SH ? ISD : ID;
    const int tid = threadIdx.x, l = tid & 31, wid = tid >> 5;
    const int m0 = blockIdx.x * 128, n0 = blockIdx.y * 64;
    const int e = SH ? 0 : blockIdx.z;
    int cnt = TT;
    if (!SH) { cnt = g_count[e]; if (m0 >= cnt) return; }

    const __half* Bg = (SH ? g_Sg16 : g_Wg16 + (size_t)e * HD * ID) + n0;
    const __half* Bu = (SH ? g_Su16 : g_Wu16 + (size_t)e * HD * ID) + n0;

    size_t aoff[4];
#pragma unroll
    for (int p = 0; p < 4; p++) {
        int idx = m0 + p * 32 + (tid >> 3);
        if (!SH) {
            int ci = idx < cnt ? idx : cnt - 1;
            aoff[p] = (size_t)g_tok[e][ci] * HD;
        } else {
            aoff[p] = (size_t)idx * HD;
        }
    }

    extern __shared__ char dyn[];
    unsigned sb = (s2u(dyn) + 127) & ~127u;
    const int kseg = tid & 7;

    auto LOAD = [&](int kt) {
        unsigned bb = sb + (unsigned)(kt % 3) * GU_STG;
        int k0 = kt * 64;
#pragma unroll
        for (int i = 0; i < 4; i++) {
            unsigned d = swz((unsigned)(i * 32 + (tid >> 3)) * 128 + kseg * 16);
            cpasync16(bb + GU_A + d, g_x16 + aoff[i] + k0 + kseg * 8);
        }
#pragma unroll
        for (int i = 0; i < 2; i++) {
            int s = i * 256 + tid;
            int kk = s >> 3, c8 = s & 7;
            unsigned d = swz((unsigned)kk * 128 + c8 * 16);
            size_t o = (size_t)(k0 + kk) * N_TOT + c8 * 8;
            cpasync16(bb + GU_BG + d, Bg + o);
            cpasync16(bb + GU_BU + d, Bu + o);
        }
        CP_COMMIT();
    };

    float cg[2][4][4] = {}, cu[2][4][4] = {};
    const int wm = (wid & 3) * 32, wn = (wid >> 2) * 32;
    const unsigned aRowB = (unsigned)(wm + (l & 15)) * 128;
    const unsigned sx = l & 7;
    const unsigned aCx = (l >> 4) & 1;
    const unsigned bKr = (l & 7) + ((l >> 3) & 1) * 8;
    const unsigned bG2 = (l >> 4) & 1;
    const unsigned nq = (unsigned)wn >> 3;
    const unsigned ck0 = ((nq + 0 + bG2) ^ sx) << 4;
    const unsigned ck1 = ((nq + 2 + bG2) ^ sx) << 4;

    auto COMPUTE = [&](int st) {
        unsigned bb = sb + (unsigned)st * GU_STG;
#pragma unroll
        for (int ks = 0; ks < 4; ks++) {
            unsigned cka = (((unsigned)(ks * 2) + aCx) ^ sx) << 4;
            unsigned ah[2][4];
#pragma unroll
            for (int mf = 0; mf < 2; mf++)
                ldsm4(bb + GU_A + aRowB + mf * 2048 + cka, ah[mf]);
            unsigned brow = (unsigned)(ks * 16 + bKr) * 128;
            unsigned bg[8], bu[8];
            ldsm4t(bb + GU_BG + brow + ck0, bg);
            ldsm4t(bb + GU_BG + brow + ck1, bg + 4);
            ldsm4t(bb + GU_BU + brow + ck0, bu);
            ldsm4t(bb + GU_BU + brow + ck1, bu + 4);
#pragma unroll
            for (int mf = 0; mf < 2; mf++)
#pragma unroll
                for (int nf = 0; nf < 4; nf++) {
                    mma16816(cg[mf][nf], ah[mf], bg + nf * 2);
                    mma16816(cu[mf][nf], ah[mf], bu + nf * 2);
                }
        }
    };

    LOAD(0);
    LOAD(1);
#pragma unroll 1
    for (int kt = 0; kt < NK; kt++) {
        if (kt + 1 < NK) CP_WAIT1(); else CP_WAIT0();
        __syncthreads();
        if (kt + 2 < NK) LOAD(kt + 2);
        COMPUTE(kt % 3);
    }

    const int rr = m0 + wm + (l >> 2);
    const int cc0 = n0 + wn + (l & 3) * 2;
    __half* O = SH ? g_shact : g_act;
#pragma unroll
    for (int mf = 0; mf < 2; mf++) {
#pragma unroll
        for (int h = 0; h < 2; h++) {
            int r = rr + mf * 16 + h * 8;
            size_t obase;
            if (!SH) {
                if (r >= cnt) continue;
                int flat = g_tok[e][r] * 2 + g_slot[e][r];
                obase = (size_t)flat * ID;
            } else {
                obase = (size_t)r * ISD;
            }
#pragma unroll
            for (int nf = 0; nf < 4; nf++) {
                float a0 = silu_mul(cg[mf][nf][h * 2 + 0], cu[mf][nf][h * 2 + 0]);
                float a1 = silu_mul(cg[mf][nf][h * 2 + 1], cu[mf][nf][h * 2 + 1]);
                *(unsigned*)(O + obase + cc0 + nf * 8) = pack2h(a0, a1);
            }
        }
    }
}

// =================== expert down HMMA (split-K x2; BM=128, BN=128, warp 32x64) ===================
#define DN_A 0u
#define DN_B 16384u
#define DN_STG 32768u

__global__ void __launch_bounds__(256, 2) edown_hmma() {
    const int tid = threadIdx.x, l = tid & 31, wid = tid >> 5;
    const int m0 = blockIdx.x * 128, n0 = blockIdx.y * 128;
    const int z = blockIdx.z;
    const int e = z >> 1, s = z & 1;
    const int nkt = ID / 128;          // 22
    const int kb  = s * (ID / 2);
    int cnt = g_count[e];
    if (m0 >= cnt) return;

    const __half* B = g_Wd16 + (size_t)e * ID * HD + (size_t)kb * HD + n0;

    size_t aoff[4];
#pragma unroll
    for (int p = 0; p < 4; p++) {
        int idx = m0 + p * 32 + (tid >> 3);
        int ci = idx < cnt ? idx : cnt - 1;
        aoff[p] = (size_t)(g_tok[e][ci] * 2 + g_slot[e][ci]) * ID + kb;
    }

    extern __shared__ char dyn[];
    unsigned sb = (s2u(dyn) + 127) & ~127u;
    const int kseg = tid & 7;

    auto LOAD = [&](int kt) {
        unsigned bb = sb + (unsigned)(kt % 3) * DN_STG;
        int k0 = kt * 64;
#pragma unroll
        for (int i = 0; i < 4; i++) {
            unsigned d = swz((unsigned)(i * 32 + (tid >> 3)) * 128 + kseg * 16);
            cpasync16(bb + DN_A + d, g_act + aoff[i] + k0 + kseg * 8);
        }
#pragma unroll
        for (int i = 0; i < 4; i++) {
            int sidx = i * 256 + tid;
            int kk = sidx >> 4, c16 = sidx & 15;
            unsigned d = (unsigned)(c16 >> 3) * 8192 + swz((unsigned)kk * 128 + (c16 & 7) * 16);
            cpasync16(bb + DN_B + d, B + (size_t)(k0 + kk) * HD + c16 * 8);
        }
        CP_COMMIT();
    };

    float cc[2][8][4] = {};
    const int wm = (wid & 3) * 32, wn = (wid >> 2) * 64;
    const unsigned aRowB = (unsigned)(wm + (l & 15)) * 128;
    const unsigned sx = l & 7;
    const unsigned aCx = (l >> 4) & 1;
    const unsigned bKr = (l & 7) + ((l >> 3) & 1) * 8;
    const unsigned bG2 = (l >> 4) & 1;
    const unsigned hoff = (unsigned)(wn >> 6) * 8192;
    unsigned ck[4];
#pragma unroll
    for (int j = 0; j < 4; j++) ck[j] = (((unsigned)(2 * j) + bG2) ^ sx) << 4;

    auto COMPUTE = [&](int st) {
        unsigned bb = sb + (unsigned)st * DN_STG;
#pragma unroll
        for (int ks = 0; ks < 4; ks++) {
            unsigned cka = (((unsigned)(ks * 2) + aCx) ^ sx) << 4;
            unsigned ah[2][4];
#pragma unroll
            for (int mf = 0; mf < 2; mf++)
                ldsm4(bb + DN_A + aRowB + mf * 2048 + cka, ah[mf]);
            unsigned brow = (unsigned)(ks * 16 + bKr) * 128;
            unsigned bh[16];
#pragma unroll
            for (int j = 0; j < 4; j++)
                ldsm4t(bb + DN_B + hoff + brow + ck[j], bh + 4 * j);
#pragma unroll
            for (int mf = 0; mf < 2; mf++)
#pragma unroll
                for (int nf = 0; nf < 8; nf++)
                    mma16816(cc[mf][nf], ah[mf], bh + nf * 2);
        }
    };

    LOAD(0);
    LOAD(1);
#pragma unroll 1
    for (int kt = 0; kt < nkt; kt++) {
        if (kt + 1 < nkt) CP_WAIT1(); else CP_WAIT0();
        __syncthreads();
        if (kt + 2 < nkt) LOAD(kt + 2);
        COMPUTE(kt % 3);
    }

    const int rr = m0 + wm + (l >> 2);
    const int cc0 = n0 + wn + (l & 3) * 2;
    float* OutP = s ? g_dp1 : g_dp0;
#pragma unroll
    for (int mf = 0; mf < 2; mf++) {
#pragma unroll
        for (int h = 0; h < 2; h++) {
            int r = rr + mf * 16 + h * 8;
            if (r >= cnt) continue;
            int tok = g_tok[e][r], slot = g_slot[e][r];
            float pw = g_p[tok][slot];
            size_t base = (size_t)(tok * 2 + slot) * HD;
#pragma unroll
            for (int nf = 0; nf < 8; nf++) {
                size_t off = base + cc0 + nf * 8;
                *(float2*)(OutP + off) =
                    make_float2(pw * cc[mf][nf][h * 2 + 0], pw * cc[mf][nf][h * 2 + 1]);
            }
        }
    }
}

// =================== shared down HMMA (BM=64, BN=128, warp 32x32) -> writes out ===================
#define SD_A 0u
#define SD_B 8192u
#define SD_STG 24576u

__global__ void __launch_bounds__(256, 2) sdown_hmma(float* __restrict__ Out) {
    constexpr int NK = ISD / 64;       // 22
    const int tid = threadIdx.x, l = tid & 31, wid = tid >> 5;
    const int m0 = blockIdx.x * 64, n0 = blockIdx.y * 128;

    const __half* B = g_Sd16 + n0;

    size_t aoff[2];
#pragma unroll
    for (int p = 0; p < 2; p++) {
        int idx = m0 + p * 32 + (tid >> 3);
        aoff[p] = (size_t)idx * ISD;
    }

    extern __shared__ char dyn[];
    unsigned sb = (s2u(dyn) + 127) & ~127u;
    const int kseg = tid & 7;

    auto LOAD = [&](int kt) {
        unsigned bb = sb + (unsigned)(kt % 3) * SD_STG;
        int k0 = kt * 64;
#pragma unroll
        for (int i = 0; i < 2; i++) {
            unsigned d = swz((unsigned)(i * 32 + (tid >> 3)) * 128 + kseg * 16);
            cpasync16(bb + SD_A + d, g_shact + aoff[i] + k0 + kseg * 8);
        }
#pragma unroll
        for (int i = 0; i < 4; i++) {
            int sidx = i * 256 + tid;
            int kk = sidx >> 4, c16 = sidx & 15;
            unsigned d = (unsigned)(c16 >> 3) * 8192 + swz((unsigned)kk * 128 + (c16 & 7) * 16);
            cpasync16(bb + SD_B + d, B + (size_t)(k0 + kk) * HD + c16 * 8);
        }
        CP_COMMIT();
    };

    float cc[2][4][4] = {};
    const int wm = (wid & 1) * 32, wn = (wid >> 1) * 32;
    const unsigned aRowB = (unsigned)(wm + (l & 15)) * 128;
    const unsigned sx = l & 7;
    const unsigned aCx = (l >> 4) & 1;
    const unsigned bKr = (l & 7) + ((l >> 3) & 1) * 8;
    const unsigned bG2 = (l >> 4) & 1;
    const unsigned hoff = (unsigned)(wn >> 6) * 8192;
    const unsigned nq = ((unsigned)wn & 63) >> 3;
    const unsigned ck0 = ((nq + 0 + bG2) ^ sx) << 4;
    const unsigned ck1 = ((nq + 2 + bG2) ^ sx) << 4;

    auto COMPUTE = [&](int st) {
        unsigned bb = sb + (unsigned)st * SD_STG;
#pragma unroll
        for (int ks = 0; ks < 4; ks++) {
            unsigned cka = (((unsigned)(ks * 2) + aCx) ^ sx) << 4;
            unsigned ah[2][4];
#pragma unroll
            for (int mf = 0; mf < 2; mf++)
                ldsm4(bb + SD_A + aRowB + mf * 2048 + cka, ah[mf]);
            unsigned brow = (unsigned)(ks * 16 + bKr) * 128;
            unsigned bh[8];
            ldsm4t(bb + SD_B + hoff + brow + ck0, bh);
            ldsm4t(bb + SD_B + hoff + brow + ck1, bh + 4);
#pragma unroll
            for (int mf = 0; mf < 2; mf++)
#pragma unroll
                for (int nf = 0; nf < 4; nf++)
                    mma16816(cc[mf][nf], ah[mf], bh + nf * 2);
        }
    };

    LOAD(0);
    LOAD(1);
#pragma unroll 1
    for (int kt = 0; kt < NK; kt++) {
        if (kt + 1 < NK) CP_WAIT1(); else CP_WAIT0();
        __syncthreads();
        if (kt + 2 < NK) LOAD(kt + 2);
        COMPUTE(kt % 3);
    }

    const int rr = m0 + wm + (l >> 2);
    const int cc0 = n0 + wn + (l & 3) * 2;
#pragma unroll
    for (int mf = 0; mf < 2; mf++) {
#pragma unroll
        for (int h = 0; h < 2; h++) {
            int r = rr + mf * 16 + h * 8;
#pragma unroll
            for (int nf = 0; nf < 4; nf++) {
                int col = cc0 + nf * 8;
                *(float2*)(Out + (size_t)r * HD + col) =
                    make_float2(cc[mf][nf][h * 2 + 0], cc[mf][nf][h * 2 + 1]);
            }
        }
    }
}

// =================== final combine: out += dp0[2t]+dp0[2t+1]+dp1[2t]+dp1[2t+1] ===================
__global__ void combine_kernel(float4* __restrict__ out) {
    int i = blockIdx.x * blockDim.x + threadIdx.x;
    if (i >= TT * HD / 4) return;
    int t  = i / (HD / 4);
    int c4 = i & (HD / 4 - 1);
    size_t b0 = (size_t)(2 * t) * (HD / 4) + c4;
    size_t b1 = b0 + (HD / 4);
    float4 s  = out[i];
    float4 a0 = ((const float4*)g_dp0)[b0];
    float4 a1 = ((const float4*)g_dp0)[b1];
    float4 a2 = ((const float4*)g_dp1)[b0];
    float4 a3 = ((const float4*)g_dp1)[b1];
    float4 o;
    o.x = s.x + a0.x + a1.x + a2.x + a3.x;
    o.y = s.y + a0.y + a1.y + a2.y + a3.y;
    o.z = s.z + a0.z + a1.z + a2.z + a3.z;
    o.w = s.w + a0.w + a1.w + a2.w + a3.w;
    out[i] = o;
}

// =================== launch (dual independent paths, graph-capturable) ===================
extern "C" void kernel_launch(void* const* d_in, const int* in_sizes, int n_in,
                              void* d_out, int out_size) {
    const float* x      = (const float*)d_in[0];
    const float* gate_w = (const float*)d_in[1];
    const float* Wg     = (const float*)d_in[2];
    const float* Wu     = (const float*)d_in[3];
    const float* Wd     = (const float*)d_in[4];
    const float* Sg     = (const float*)d_in[5];
    const float* Su     = (const float*)d_in[6];
    const float* Sd     = (const float*)d_in[7];
    float* out = (float*)d_out;

    static cudaStream_t s2 = nullptr;
    static cudaEvent_t evF = nullptr, evR = nullptr, evA = nullptr, evB = nullptr, evS = nullptr;
    if (!s2) {
        cudaStreamCreateWithFlags(&s2, cudaStreamNonBlocking);
        cudaEventCreateWithFlags(&evF, cudaEventDisableTiming);
        cudaEventCreateWithFlags(&evR, cudaEventDisableTiming);
        cudaEventCreateWithFlags(&evA, cudaEventDisableTiming);
        cudaEventCreateWithFlags(&evB, cudaEventDisableTiming);
        cudaEventCreateWithFlags(&evS, cudaEventDisableTiming);
        cudaFuncSetAttribute(gateup_hmma<false>, cudaFuncAttributeMaxDynamicSharedMemorySize, 3 * 32768 + 128);
        cudaFuncSetAttribute(gateup_hmma<true>,  cudaFuncAttributeMaxDynamicSharedMemorySize, 3 * 32768 + 128);
        cudaFuncSetAttribute(edown_hmma,         cudaFuncAttributeMaxDynamicSharedMemorySize, 3 * 32768 + 128);
        cudaFuncSetAttribute(sdown_hmma,         cudaFuncAttributeMaxDynamicSharedMemorySize, 3 * 24576 + 128);
    }

    // fork side stream
    cudaEventRecord(evF, 0);
    cudaStreamWaitEvent(s2, evF, 0);

    // side: zero -> router -> conv_b(Wd,Sg,Su,Sd) -> [wait x16] shared gateup -> shared down -> out
    zero_counts_kernel<<<1, 32, 0, s2>>>();
    router_kernel<<<TT / 256, 256, 0, s2>>>(x, gate_w);
    cudaEventRecord(evR, s2);
    conv_b<<<(CONVB_TOTAL + 255) / 256, 256, 0, s2>>>(
        (const float4*)Wd, (const float4*)Sg, (const float4*)Su, (const float4*)Sd);
    cudaEventRecord(evB, s2);

    // main: conv_a(x,Wg,Wu)
    conv_a<<<(CONVA_TOTAL + 255) / 256, 256>>>(
        (const float4*)x, (const float4*)Wg, (const float4*)Wu);
    cudaEventRecord(evA, 0);

    // side: shared path (needs x16 from conv_a)
    cudaStreamWaitEvent(s2, evA, 0);
    dim3 gSGU(TT / 128, ISD / 64);
    gateup_hmma<true><<<gSGU, 256, 3 * 32768 + 128, s2>>>();
    dim3 gSD(TT / 64, HD / 128);
    sdown_hmma<<<gSD, 256, 3 * 24576 + 128, s2>>>(out);
    cudaEventRecord(evS, s2);

    // main: expert path (needs router lists)
    cudaStreamWaitEvent(0, evR, 0);
    dim3 gGU(TT / 128, ID / 64, NE);
    gateup_hmma<false><<<gGU, 256, 3 * 32768 + 128>>>();

    cudaStreamWaitEvent(0, evB, 0);   // Wd16 ready
    dim3 gD(TT / 128, HD / 128, 2 * NE);
    edown_hmma<<<gD, 256, 3 * 32768 + 128>>>();

    // join: combine expert partials into out
    cudaStreamWaitEvent(0, evS, 0);
    combine_kernel<<<(TT * HD / 4 + 255) / 256, 256>>>((float4*)out);
}

// round 16
// speedup vs baseline: 2.1670x; 1.0083x over previous
#include <cuda_runtime.h>
#include <cuda_fp16.h>
#include <math.h>

#define TT   2048
#define HD   1024
#define ID   2816
#define NE   8
#define ISD  1408

// ---- routing scratch ----
__device__ int   g_count[NE];
__device__ int   g_tok[NE][TT];
__device__ int   g_slot[NE][TT];
__device__ float g_p[TT][2];
__device__ float g_dp0[(size_t)TT * 2 * HD];   // expert split-K partial 0 (p-weighted)
__device__ float g_dp1[(size_t)TT * 2 * HD];   // expert split-K partial 1 (p-weighted)
__device__ float g_shp0[(size_t)TT * HD];      // shared split-K partial 0
__device__ float g_shp1[(size_t)TT * HD];      // shared split-K partial 1

// ---- fp16 operands ----
__device__ __half g_Wg16[(size_t)NE * HD * ID];
__device__ __half g_Wu16[(size_t)NE * HD * ID];
__device__ __half g_Wd16[(size_t)NE * ID * HD];
__device__ __half g_Sg16[(size_t)HD * ISD];
__device__ __half g_Su16[(size_t)HD * ISD];
__device__ __half g_Sd16[(size_t)ISD * HD];
__device__ __half g_x16[(size_t)TT * HD];
__device__ __half g_act[(size_t)TT * 2 * ID];
__device__ __half g_shact[(size_t)TT * ISD];

// =================== helpers ===================
__device__ __forceinline__ unsigned s2u(const void* p) {
    return (unsigned)__cvta_generic_to_shared(p);
}
__device__ __forceinline__ unsigned swz(unsigned o) { return o ^ ((o >> 3) & 0x70); }

__device__ __forceinline__ unsigned pack2h(float f0, float f1) {
    __half2 h = __floats2half2_rn(f0, f1);
    return *(unsigned*)&h;
}
__device__ __forceinline__ void cpasync16(unsigned s, const void* g) {
    asm volatile("cp.async.cg.shared.global [%0], [%1], 16;" :: "r"(s), "l"(g));
}
#define CP_COMMIT() asm volatile("cp.async.commit_group;" ::: "memory")
#define CP_WAIT1()  asm volatile("cp.async.wait_group 1;"  ::: "memory")
#define CP_WAIT0()  asm volatile("cp.async.wait_group 0;"  ::: "memory")

__device__ __forceinline__ void ldsm4(unsigned a, unsigned* r) {
    asm volatile("ldmatrix.sync.aligned.m8n8.x4.shared.b16 {%0,%1,%2,%3}, [%4];"
                 : "=r"(r[0]), "=r"(r[1]), "=r"(r[2]), "=r"(r[3]) : "r"(a));
}
__device__ __forceinline__ void ldsm4t(unsigned a, unsigned* r) {
    asm volatile("ldmatrix.sync.aligned.m8n8.x4.trans.shared.b16 {%0,%1,%2,%3}, [%4];"
                 : "=r"(r[0]), "=r"(r[1]), "=r"(r[2]), "=r"(r[3]) : "r"(a));
}
__device__ __forceinline__ void mma16816(float* c, const unsigned* a, const unsigned* b) {
    asm volatile("mma.sync.aligned.m16n8k16.row.col.f32.f16.f16.f32 "
                 "{%0,%1,%2,%3}, {%4,%5,%6,%7}, {%8,%9}, {%0,%1,%2,%3};"
                 : "+f"(c[0]), "+f"(c[1]), "+f"(c[2]), "+f"(c[3])
                 : "r"(a[0]), "r"(a[1]), "r"(a[2]), "r"(a[3]), "r"(b[0]), "r"(b[1]));
}
__device__ __forceinline__ float silu_mul(float g, float u) {
    return u * g / (1.f + __expf(-g));
}

// =================== conversion kernels ===================
#define NXC (TT * HD / 8)
#define NWC (NE * HD * ID / 8)
#define NSC (HD * ISD / 8)

// main-stream: x, Wg, Wu
__global__ void conv_a(const float4* __restrict__ x, const float4* __restrict__ wg,
                       const float4* __restrict__ wu) {
    long i = (long)blockIdx.x * blockDim.x + threadIdx.x;
    const float4* src; __half* dst;
    if (i < NXC)               { src = x;  dst = g_x16; }
    else if ((i -= NXC) < NWC) { src = wg; dst = g_Wg16; }
    else if ((i -= NWC) < NWC) { src = wu; dst = g_Wu16; }
    else return;
    float4 a = src[2 * i], b = src[2 * i + 1];
    uint4 o;
    o.x = pack2h(a.x, a.y);
    o.y = pack2h(a.z, a.w);
    o.z = pack2h(b.x, b.y);
    o.w = pack2h(b.z, b.w);
    ((uint4*)dst)[i] = o;
}
#define CONVA_TOTAL (NXC + 2 * NWC)

// side-stream: Wd, Sg, Su, Sd
__global__ void conv_b(const float4* __restrict__ wd, const float4* __restrict__ sg,
                       const float4* __restrict__ su, const float4* __restrict__ sd) {
    long i = (long)blockIdx.x * blockDim.x + threadIdx.x;
    const float4* src; __half* dst;
    if (i < NWC)               { src = wd; dst = g_Wd16; }
    else if ((i -= NWC) < NSC) { src = sg; dst = g_Sg16; }
    else if ((i -= NSC) < NSC) { src = su; dst = g_Su16; }
    else if ((i -= NSC) < NSC) { src = sd; dst = g_Sd16; }
    else return;
    float4 a = src[2 * i], b = src[2 * i + 1];
    uint4 o;
    o.x = pack2h(a.x, a.y);
    o.y = pack2h(a.z, a.w);
    o.z = pack2h(b.x, b.y);
    o.w = pack2h(b.z, b.w);
    ((uint4*)dst)[i] = o;
}
#define CONVB_TOTAL (NWC + 3 * NSC)

// =================== router ===================
__global__ void zero_counts_kernel() { if (threadIdx.x < NE) g_count[threadIdx.x] = 0; }

__global__ void router_kernel(const float* __restrict__ x, const float* __restrict__ gw) {
    int t = blockIdx.x * blockDim.x + threadIdx.x;
    if (t >= TT) return;
    float lg[NE];
#pragma unroll
    for (int e = 0; e < NE; e++) lg[e] = 0.f;
    const float* xr = x + (size_t)t * HD;
    for (int h = 0; h < HD; h++) {
        float xv = xr[h];
#pragma unroll
        for (int e = 0; e < NE; e++) lg[e] = fmaf(xv, gw[h * NE + e], lg[e]);
    }
    int i0 = 0; float v0 = lg[0];
#pragma unroll
    for (int e = 1; e < NE; e++) if (lg[e] > v0) { v0 = lg[e]; i0 = e; }
    int i1 = -1; float v1 = -INFINITY;
#pragma unroll
    for (int e = 0; e < NE; e++) if (e != i0 && lg[e] > v1) { v1 = lg[e]; i1 = e; }
    float e1 = expf(v1 - v0);
    float inv = 1.f / (1.f + e1);
    g_p[t][0] = inv;
    g_p[t][1] = e1 * inv;
    int p0 = atomicAdd(&g_count[i0], 1);
    g_tok[i0][p0] = t; g_slot[i0][p0] = 0;
    int p1 = atomicAdd(&g_count[i1], 1);
    g_tok[i1][p1] = t; g_slot[i1][p1] = 1;
}

// =================== gate+up HMMA (256 thr, BM=128, BN=64, 2 CTAs/SM) ===================
#define GU_A  0u
#define GU_BG 16384u
#define GU_BU 24576u
#define GU_STG 32768u

template<bool SH>
__global__ void __launch_bounds__(256, 2) gateup_hmma() {
    constexpr int NK = HD / 64;
    constexpr int N_TOT = SH ? ISD : ID;
    const int tid = threadIdx.x, l = tid & 31, wid = tid >> 5;
    const int m0 = blockIdx.x * 128, n0 = blockIdx.y * 64;
    const int e = SH ? 0 : blockIdx.z;
    int cnt = TT;
    if (!SH) { cnt = g_count[e]; if (m0 >= cnt) return; }

    const __half* Bg = (SH ? g_Sg16 : g_Wg16 + (size_t)e * HD * ID) + n0;
    const __half* Bu = (SH ? g_Su16 : g_Wu16 + (size_t)e * HD * ID) + n0;

    size_t aoff[4];
#pragma unroll
    for (int p = 0; p < 4; p++) {
        int idx = m0 + p * 32 + (tid >> 3);
        if (!SH) {
            int ci = idx < cnt ? idx : cnt - 1;
            aoff[p] = (size_t)g_tok[e][ci] * HD;
        } else {
            aoff[p] = (size_t)idx * HD;
        }
    }

    extern __shared__ char dyn[];
    unsigned sb = (s2u(dyn) + 127) & ~127u;
    const int kseg = tid & 7;

    auto LOAD = [&](int kt) {
        unsigned bb = sb + (unsigned)(kt % 3) * GU_STG;
        int k0 = kt * 64;
#pragma unroll
        for (int i = 0; i < 4; i++) {
            unsigned d = swz((unsigned)(i * 32 + (tid >> 3)) * 128 + kseg * 16);
            cpasync16(bb + GU_A + d, g_x16 + aoff[i] + k0 + kseg * 8);
        }
#pragma unroll
        for (int i = 0; i < 2; i++) {
            int s = i * 256 + tid;
            int kk = s >> 3, c8 = s & 7;
            unsigned d = swz((unsigned)kk * 128 + c8 * 16);
            size_t o = (size_t)(k0 + kk) * N_TOT + c8 * 8;
            cpasync16(bb + GU_BG + d, Bg + o);
            cpasync16(bb + GU_BU + d, Bu + o);
        }
        CP_COMMIT();
    };

    float cg[2][4][4] = {}, cu[2][4][4] = {};
    const int wm = (wid & 3) * 32, wn = (wid >> 2) * 32;
    const unsigned aRowB = (unsigned)(wm + (l & 15)) * 128;
    const unsigned sx = l & 7;
    const unsigned aCx = (l >> 4) & 1;
    const unsigned bKr = (l & 7) + ((l >> 3) & 1) * 8;
    const unsigned bG2 = (l >> 4) & 1;
    const unsigned nq = (unsigned)wn >> 3;
    const unsigned ck0 = ((nq + 0 + bG2) ^ sx) << 4;
    const unsigned ck1 = ((nq + 2 + bG2) ^ sx) << 4;

    auto COMPUTE = [&](int st) {
        unsigned bb = sb + (unsigned)st * GU_STG;
        unsigned ahAll[4][2][4];
#pragma unroll
        for (int ks = 0; ks < 4; ks++) {
            unsigned cka = (((unsigned)(ks * 2) + aCx) ^ sx) << 4;
#pragma unroll
            for (int mf = 0; mf < 2; mf++)
                ldsm4(bb + GU_A + aRowB + mf * 2048 + cka, ahAll[ks][mf]);
        }
#pragma unroll
        for (int ks = 0; ks < 4; ks++) {
            unsigned brow = (unsigned)(ks * 16 + bKr) * 128;
            unsigned bg[8], bu[8];
            ldsm4t(bb + GU_BG + brow + ck0, bg);
            ldsm4t(bb + GU_BG + brow + ck1, bg + 4);
            ldsm4t(bb + GU_BU + brow + ck0, bu);
            ldsm4t(bb + GU_BU + brow + ck1, bu + 4);
#pragma unroll
            for (int mf = 0; mf < 2; mf++)
#pragma unroll
                for (int nf = 0; nf < 4; nf++) {
                    mma16816(cg[mf][nf], ahAll[ks][mf], bg + nf * 2);
                    mma16816(cu[mf][nf], ahAll[ks][mf], bu + nf * 2);
                }
        }
    };

    LOAD(0);
    LOAD(1);
#pragma unroll 1
    for (int kt = 0; kt < NK; kt++) {
        if (kt + 1 < NK) CP_WAIT1(); else CP_WAIT0();
        __syncthreads();
        if (kt + 2 < NK) LOAD(kt + 2);
        COMPUTE(kt % 3);
    }

    const int rr = m0 + wm + (l >> 2);
    const int cc0 = n0 + wn + (l & 3) * 2;
    __half* O = SH ? g_shact : g_act;
#pragma unroll
    for (int mf = 0; mf < 2; mf++) {
#pragma unroll
        for (int h = 0; h < 2; h++) {
            int r = rr + mf * 16 + h * 8;
            size_t obase;
            if (!SH) {
                if (r >= cnt) continue;
                int flat = g_tok[e][r] * 2 + g_slot[e][r];
                obase = (size_t)flat * ID;
            } else {
                obase = (size_t)r * ISD;
            }
#pragma unroll
            for (int nf = 0; nf < 4; nf++) {
                float a0 = silu_mul(cg[mf][nf][h * 2 + 0], cu[mf][nf][h * 2 + 0]);
                float a1 = silu_mul(cg[mf][nf][h * 2 + 1], cu[mf][nf][h * 2 + 1]);
                *(unsigned*)(O + obase + cc0 + nf * 8) = pack2h(a0, a1);
            }
        }
    }
}

// =================== expert down HMMA (split-K x2; BM=128, BN=128, warp 32x64) ===================
#define DN_A 0u
#define DN_B 16384u
#define DN_STG 32768u

__global__ void __launch_bounds__(256, 2) edown_hmma() {
    const int tid = threadIdx.x, l = tid & 31, wid = tid >> 5;
    const int m0 = blockIdx.x * 128, n0 = blockIdx.y * 128;
    const int z = blockIdx.z;
    const int e = z >> 1, s = z & 1;
    const int nkt = ID / 128;          // 22
    const int kb  = s * (ID / 2);
    int cnt = g_count[e];
    if (m0 >= cnt) return;

    const __half* B = g_Wd16 + (size_t)e * ID * HD + (size_t)kb * HD + n0;

    size_t aoff[4];
#pragma unroll
    for (int p = 0; p < 4; p++) {
        int idx = m0 + p * 32 + (tid >> 3);
        int ci = idx < cnt ? idx : cnt - 1;
        aoff[p] = (size_t)(g_tok[e][ci] * 2 + g_slot[e][ci]) * ID + kb;
    }

    extern __shared__ char dyn[];
    unsigned sb = (s2u(dyn) + 127) & ~127u;
    const int kseg = tid & 7;

    auto LOAD = [&](int kt) {
        unsigned bb = sb + (unsigned)(kt % 3) * DN_STG;
        int k0 = kt * 64;
#pragma unroll
        for (int i = 0; i < 4; i++) {
            unsigned d = swz((unsigned)(i * 32 + (tid >> 3)) * 128 + kseg * 16);
            cpasync16(bb + DN_A + d, g_act + aoff[i] + k0 + kseg * 8);
        }
#pragma unroll
        for (int i = 0; i < 4; i++) {
            int sidx = i * 256 + tid;
            int kk = sidx >> 4, c16 = sidx & 15;
            unsigned d = (unsigned)(c16 >> 3) * 8192 + swz((unsigned)kk * 128 + (c16 & 7) * 16);
            cpasync16(bb + DN_B + d, B + (size_t)(k0 + kk) * HD + c16 * 8);
        }
        CP_COMMIT();
    };

    float cc[2][8][4] = {};
    const int wm = (wid & 3) * 32, wn = (wid >> 2) * 64;
    const unsigned aRowB = (unsigned)(wm + (l & 15)) * 128;
    const unsigned sx = l & 7;
    const unsigned aCx = (l >> 4) & 1;
    const unsigned bKr = (l & 7) + ((l >> 3) & 1) * 8;
    const unsigned bG2 = (l >> 4) & 1;
    const unsigned hoff = (unsigned)(wn >> 6) * 8192;
    unsigned ck[4];
#pragma unroll
    for (int j = 0; j < 4; j++) ck[j] = (((unsigned)(2 * j) + bG2) ^ sx) << 4;

    auto COMPUTE = [&](int st) {
        unsigned bb = sb + (unsigned)st * DN_STG;
        unsigned ahAll[4][2][4];
#pragma unroll
        for (int ks = 0; ks < 4; ks++) {
            unsigned cka = (((unsigned)(ks * 2) + aCx) ^ sx) << 4;
#pragma unroll
            for (int mf = 0; mf < 2; mf++)
                ldsm4(bb + DN_A + aRowB + mf * 2048 + cka, ahAll[ks][mf]);
        }
#pragma unroll
        for (int ks = 0; ks < 4; ks++) {
            unsigned brow = (unsigned)(ks * 16 + bKr) * 128;
            unsigned bh[16];
#pragma unroll
            for (int j = 0; j < 4; j++)
                ldsm4t(bb + DN_B + hoff + brow + ck[j], bh + 4 * j);
#pragma unroll
            for (int mf = 0; mf < 2; mf++)
#pragma unroll
                for (int nf = 0; nf < 8; nf++)
                    mma16816(cc[mf][nf], ahAll[ks][mf], bh + nf * 2);
        }
    };

    LOAD(0);
    LOAD(1);
#pragma unroll 1
    for (int kt = 0; kt < nkt; kt++) {
        if (kt + 1 < nkt) CP_WAIT1(); else CP_WAIT0();
        __syncthreads();
        if (kt + 2 < nkt) LOAD(kt + 2);
        COMPUTE(kt % 3);
    }

    const int rr = m0 + wm + (l >> 2);
    const int cc0 = n0 + wn + (l & 3) * 2;
    float* OutP = s ? g_dp1 : g_dp0;
#pragma unroll
    for (int mf = 0; mf < 2; mf++) {
#pragma unroll
        for (int h = 0; h < 2; h++) {
            int r = rr + mf * 16 + h * 8;
            if (r >= cnt) continue;
            int tok = g_tok[e][r], slot = g_slot[e][r];
            float pw = g_p[tok][slot];
            size_t base = (size_t)(tok * 2 + slot) * HD;
#pragma unroll
            for (int nf = 0; nf < 8; nf++) {
                size_t off = base + cc0 + nf * 8;
                *(float2*)(OutP + off) =
                    make_float2(pw * cc[mf][nf][h * 2 + 0], pw * cc[mf][nf][h * 2 + 1]);
            }
        }
    }
}

// =================== shared down HMMA (split-K x2; BM=64, BN=128, warp 32x32) ===================
#define SD_A 0u
#define SD_B 8192u
#define SD_STG 24576u

__global__ void __launch_bounds__(256, 2) sdown_hmma() {
    constexpr int NK = (ISD / 2) / 64;   // 11
    const int tid = threadIdx.x, l = tid & 31, wid = tid >> 5;
    const int m0 = blockIdx.x * 64, n0 = blockIdx.y * 128;
    const int s = blockIdx.z;
    const int kb = s * (ISD / 2);

    const __half* B = g_Sd16 + (size_t)kb * HD + n0;

    size_t aoff[2];
#pragma unroll
    for (int p = 0; p < 2; p++) {
        int idx = m0 + p * 32 + (tid >> 3);
        aoff[p] = (size_t)idx * ISD + kb;
    }

    extern __shared__ char dyn[];
    unsigned sb = (s2u(dyn) + 127) & ~127u;
    const int kseg = tid & 7;

    auto LOAD = [&](int kt) {
        unsigned bb = sb + (unsigned)(kt % 3) * SD_STG;
        int k0 = kt * 64;
#pragma unroll
        for (int i = 0; i < 2; i++) {
            unsigned d = swz((unsigned)(i * 32 + (tid >> 3)) * 128 + kseg * 16);
            cpasync16(bb + SD_A + d, g_shact + aoff[i] + k0 + kseg * 8);
        }
#pragma unroll
        for (int i = 0; i < 4; i++) {
            int sidx = i * 256 + tid;
            int kk = sidx >> 4, c16 = sidx & 15;
            unsigned d = (unsigned)(c16 >> 3) * 8192 + swz((unsigned)kk * 128 + (c16 & 7) * 16);
            cpasync16(bb + SD_B + d, B + (size_t)(k0 + kk) * HD + c16 * 8);
        }
        CP_COMMIT();
    };

    float cc[2][4][4] = {};
    const int wm = (wid & 1) * 32, wn = (wid >> 1) * 32;
    const unsigned aRowB = (unsigned)(wm + (l & 15)) * 128;
    const unsigned sx = l & 7;
    const unsigned aCx = (l >> 4) & 1;
    const unsigned bKr = (l & 7) + ((l >> 3) & 1) * 8;
    const unsigned bG2 = (l >> 4) & 1;
    const unsigned hoff = (unsigned)(wn >> 6) * 8192;
    const unsigned nq = ((unsigned)wn & 63) >> 3;
    const unsigned ck0 = ((nq + 0 + bG2) ^ sx) << 4;
    const unsigned ck1 = ((nq + 2 + bG2) ^ sx) << 4;

    auto COMPUTE = [&](int st) {
        unsigned bb = sb + (unsigned)st * SD_STG;
        unsigned ahAll[4][2][4];
#pragma unroll
        for (int ks = 0; ks < 4; ks++) {
            unsigned cka = (((unsigned)(ks * 2) + aCx) ^ sx) << 4;
#pragma unroll
            for (int mf = 0; mf < 2; mf++)
                ldsm4(bb + SD_A + aRowB + mf * 2048 + cka, ahAll[ks][mf]);
        }
#pragma unroll
        for (int ks = 0; ks < 4; ks++) {
            unsigned brow = (unsigned)(ks * 16 + bKr) * 128;
            unsigned bh[8];
            ldsm4t(bb + SD_B + hoff + brow + ck0, bh);
            ldsm4t(bb + SD_B + hoff + brow + ck1, bh + 4);
#pragma unroll
            for (int mf = 0; mf < 2; mf++)
#pragma unroll
                for (int nf = 0; nf < 4; nf++)
                    mma16816(cc[mf][nf], ahAll[ks][mf], bh + nf * 2);
        }
    };

    LOAD(0);
    LOAD(1);
#pragma unroll 1
    for (int kt = 0; kt < NK; kt++) {
        if (kt + 1 < NK) CP_WAIT1(); else CP_WAIT0();
        __syncthreads();
        if (kt + 2 < NK) LOAD(kt + 2);
        COMPUTE(kt % 3);
    }

    const int rr = m0 + wm + (l >> 2);
    const int cc0 = n0 + wn + (l & 3) * 2;
    float* OutP = s ? g_shp1 : g_shp0;
#pragma unroll
    for (int mf = 0; mf < 2; mf++) {
#pragma unroll
        for (int h = 0; h < 2; h++) {
            int r = rr + mf * 16 + h * 8;
#pragma unroll
            for (int nf = 0; nf < 4; nf++) {
                int col = cc0 + nf * 8;
                *(float2*)(OutP + (size_t)r * HD + col) =
                    make_float2(cc[mf][nf][h * 2 + 0], cc[mf][nf][h * 2 + 1]);
            }
        }
    }
}

// =================== final combine ===================
__global__ void combine_kernel(float4* __restrict__ out) {
    int i = blockIdx.x * blockDim.x + threadIdx.x;
    if (i >= TT * HD / 4) return;
    int t  = i / (HD / 4);
    int c4 = i & (HD / 4 - 1);
    size_t b0 = (size_t)(2 * t) * (HD / 4) + c4;
    size_t b1 = b0 + (HD / 4);
    float4 s0 = ((const float4*)g_shp0)[i];
    float4 s1 = ((const float4*)g_shp1)[i];
    float4 a0 = ((const float4*)g_dp0)[b0];
    float4 a1 = ((const float4*)g_dp0)[b1];
    float4 a2 = ((const float4*)g_dp1)[b0];
    float4 a3 = ((const float4*)g_dp1)[b1];
    float4 o;
    o.x = s0.x + s1.x + a0.x + a1.x + a2.x + a3.x;
    o.y = s0.y + s1.y + a0.y + a1.y + a2.y + a3.y;
    o.z = s0.z + s1.z + a0.z + a1.z + a2.z + a3.z;
    o.w = s0.w + s1.w + a0.w + a1.w + a2.w + a3.w;
    out[i] = o;
}

// =================== launch (dual streams; gateupE is submission #4 for ncu) ===================
extern "C" void kernel_launch(void* const* d_in, const int* in_sizes, int n_in,
                              void* d_out, int out_size) {
    const float* x      = (const float*)d_in[0];
    const float* gate_w = (const float*)d_in[1];
    const float* Wg     = (const float*)d_in[2];
    const float* Wu     = (const float*)d_in[3];
    const float* Wd     = (const float*)d_in[4];
    const float* Sg     = (const float*)d_in[5];
    const float* Su     = (const float*)d_in[6];
    const float* Sd     = (const float*)d_in[7];
    float* out = (float*)d_out;

    static cudaStream_t s2 = nullptr;
    static cudaEvent_t evF = nullptr, evR = nullptr, evA = nullptr, evB = nullptr, evS = nullptr;
    if (!s2) {
        cudaStreamCreateWithFlags(&s2, cudaStreamNonBlocking);
        cudaEventCreateWithFlags(&evF, cudaEventDisableTiming);
        cudaEventCreateWithFlags(&evR, cudaEventDisableTiming);
        cudaEventCreateWithFlags(&evA, cudaEventDisableTiming);
        cudaEventCreateWithFlags(&evB, cudaEventDisableTiming);
        cudaEventCreateWithFlags(&evS, cudaEventDisableTiming);
        cudaFuncSetAttribute(gateup_hmma<false>, cudaFuncAttributeMaxDynamicSharedMemorySize, 3 * 32768 + 128);
        cudaFuncSetAttribute(gateup_hmma<true>,  cudaFuncAttributeMaxDynamicSharedMemorySize, 3 * 32768 + 128);
        cudaFuncSetAttribute(edown_hmma,         cudaFuncAttributeMaxDynamicSharedMemorySize, 3 * 32768 + 128);
        cudaFuncSetAttribute(sdown_hmma,         cudaFuncAttributeMaxDynamicSharedMemorySize, 3 * 24576 + 128);
    }

    // fork side stream
    cudaEventRecord(evF, 0);
    cudaStreamWaitEvent(s2, evF, 0);

    // #1, #2 (side): zero -> router
    zero_counts_kernel<<<1, 32, 0, s2>>>();
    router_kernel<<<TT / 256, 256, 0, s2>>>(x, gate_w);
    cudaEventRecord(evR, s2);

    // #3 (main): conv_a(x,Wg,Wu)
    conv_a<<<(CONVA_TOTAL + 255) / 256, 256>>>(
        (const float4*)x, (const float4*)Wg, (const float4*)Wu);
    cudaEventRecord(evA, 0);

    // #4 (main, profiled): expert gate+up (needs router lists + conv_a)
    cudaStreamWaitEvent(0, evR, 0);
    dim3 gGU(TT / 128, ID / 64, NE);
    gateup_hmma<false><<<gGU, 256, 3 * 32768 + 128>>>();

    // #5 (side): conv_b(Wd,Sg,Su,Sd)
    conv_b<<<(CONVB_TOTAL + 255) / 256, 256, 0, s2>>>(
        (const float4*)Wd, (const float4*)Sg, (const float4*)Su, (const float4*)Sd);
    cudaEventRecord(evB, s2);

    // #6, #7 (side): shared gateup (needs x16) -> shared down partials
    cudaStreamWaitEvent(s2, evA, 0);
    dim3 gSGU(TT / 128, ISD / 64);
    gateup_hmma<true><<<gSGU, 256, 3 * 32768 + 128, s2>>>();
    dim3 gSD(TT / 64, HD / 128, 2);
    sdown_hmma<<<gSD, 256, 3 * 24576 + 128, s2>>>();
    cudaEventRecord(evS, s2);

    // #8 (main): expert down split-K (needs Wd16)
    cudaStreamWaitEvent(0, evB, 0);
    dim3 gD(TT / 128, HD / 128, 2 * NE);
    edown_hmma<<<gD, 256, 3 * 32768 + 128>>>();

    // #9 (main): final combine
    cudaStreamWaitEvent(0, evS, 0);
    combine_kernel<<<(TT * HD / 4 + 255) / 256, 256>>>((float4*)out);
}